// round 1
// baseline (speedup 1.0000x reference)
#include <cuda_runtime.h>
#include <cstdint>

#define NNODES 50000
#define NEDGES 800000
#define TOTEDGES (NEDGES + NNODES)
#define NEG_SLOPE 0.2f

// ---------------- scratch (allocation-free: device globals) ----------------
__device__ float g_h0[(size_t)NNODES * 128];
__device__ float g_h1[(size_t)NNODES * 128];
__device__ float g_s[NNODES * 2];
__device__ float g_t[NNODES * 2];
__device__ int   g_deg[NNODES];
__device__ int   g_rowptr[NNODES + 1];
__device__ int   g_cursor[NNODES];
__device__ int   g_col[TOTEDGES];

// ---------------- CSR build ----------------
__global__ void k_init_deg(int* __restrict__ deg, int n) {
    int i = blockIdx.x * blockDim.x + threadIdx.x;
    if (i < n) deg[i] = 1;  // self loop
}

__global__ void k_hist(const int* __restrict__ ei, int e, int* __restrict__ deg) {
    int i = blockIdx.x * blockDim.x + threadIdx.x;
    if (i < e) atomicAdd(&deg[ei[e + i]], 1);  // dst row
}

__global__ void k_scan(const int* __restrict__ deg, int* __restrict__ rowptr, int n) {
    __shared__ int sh[1024];
    __shared__ int s_run;
    int tid = threadIdx.x;
    if (tid == 0) s_run = 0;
    __syncthreads();
    for (int base = 0; base < n; base += 1024) {
        int v = (base + tid < n) ? deg[base + tid] : 0;
        sh[tid] = v;
        __syncthreads();
        for (int off = 1; off < 1024; off <<= 1) {
            int t = (tid >= off) ? sh[tid - off] : 0;
            __syncthreads();
            sh[tid] += t;
            __syncthreads();
        }
        if (base + tid < n) rowptr[base + tid + 1] = s_run + sh[tid];
        __syncthreads();
        if (tid == 0) s_run += sh[1023];
        __syncthreads();
    }
    if (tid == 0) rowptr[0] = 0;
}

__global__ void k_init_cursor(const int* __restrict__ rowptr, int* __restrict__ cursor,
                              int* __restrict__ col, int n) {
    int i = blockIdx.x * blockDim.x + threadIdx.x;
    if (i < n) {
        int p = rowptr[i];
        col[p] = i;           // self loop first
        cursor[i] = p + 1;
    }
}

__global__ void k_scatter(const int* __restrict__ ei, int e, int* __restrict__ cursor,
                          int* __restrict__ col) {
    int i = blockIdx.x * blockDim.x + threadIdx.x;
    if (i < e) {
        int s = ei[i];
        int d = ei[e + i];
        int p = atomicAdd(&cursor[d], 1);
        col[p] = s;
    }
}

// ---------------- tiled fp32 GEMM: C[M,BN] = A[M,K] @ B[K,BN] (+bias, relu) -------
template <int BN>
__global__ void __launch_bounds__(256) k_sgemm(const float* __restrict__ A,
                                               const float* __restrict__ B,
                                               float* __restrict__ C, int M, int K,
                                               const float* __restrict__ bias, int relu) {
    constexpr int BM = 128, BK = 16;
    constexpr int TN = BN / 16;
    __shared__ float As[BK][BM];
    __shared__ float Bs[BK][BN];
    int tid = threadIdx.x;
    int blockRow = blockIdx.x * BM;
    int ty = tid >> 4, tx = tid & 15;
    float acc[8][TN];
#pragma unroll
    for (int i = 0; i < 8; i++)
#pragma unroll
        for (int j = 0; j < TN; j++) acc[i][j] = 0.f;

    for (int k0 = 0; k0 < K; k0 += BK) {
        // load A tile (128x16), 512 float4 across 256 threads
#pragma unroll
        for (int l = 0; l < 2; l++) {
            int f = tid + l * 256;
            int row = f >> 2, c4 = f & 3;
            float4 v = make_float4(0.f, 0.f, 0.f, 0.f);
            int gr = blockRow + row;
            if (gr < M) v = *reinterpret_cast<const float4*>(&A[(size_t)gr * K + k0 + c4 * 4]);
            As[c4 * 4 + 0][row] = v.x;
            As[c4 * 4 + 1][row] = v.y;
            As[c4 * 4 + 2][row] = v.z;
            As[c4 * 4 + 3][row] = v.w;
        }
        // load B tile (16xBN)
        constexpr int BF4 = BK * BN / 4;
        constexpr int F4R = BN / 4;
#pragma unroll
        for (int l = 0; l < BF4 / 256; l++) {
            int f = tid + l * 256;
            int kr = f / F4R, c4 = f % F4R;
            float4 v = *reinterpret_cast<const float4*>(&B[(size_t)(k0 + kr) * BN + c4 * 4]);
            *reinterpret_cast<float4*>(&Bs[kr][c4 * 4]) = v;
        }
        __syncthreads();
#pragma unroll
        for (int kk = 0; kk < BK; kk++) {
            float a[8], b[TN];
#pragma unroll
            for (int i = 0; i < 8; i++) a[i] = As[kk][ty * 8 + i];
#pragma unroll
            for (int j = 0; j < TN; j++) b[j] = Bs[kk][tx * TN + j];
#pragma unroll
            for (int i = 0; i < 8; i++)
#pragma unroll
                for (int j = 0; j < TN; j++) acc[i][j] += a[i] * b[j];
        }
        __syncthreads();
    }
#pragma unroll
    for (int i = 0; i < 8; i++) {
        int r = blockRow + ty * 8 + i;
        if (r < M) {
#pragma unroll
            for (int j = 0; j < TN; j++) {
                int c = tx * TN + j;
                float v = acc[i][j];
                if (bias) v += bias[c];
                if (relu) v = fmaxf(v, 0.f);
                C[(size_t)r * BN + c] = v;
            }
        }
    }
}

// ---------------- per-node attention score projections ----------------
template <int H>
__global__ void k_st(const float* __restrict__ h, const float* __restrict__ a_src,
                     const float* __restrict__ a_dst, float* __restrict__ s,
                     float* __restrict__ t, int n) {
    int g = blockIdx.x * blockDim.x + threadIdx.x;
    int w = g >> 5, lane = g & 31;
    if (w >= n * H) return;
    int node = w / H, head = w % H;
    const float* hp = h + (size_t)node * (H * 64) + head * 64;
    float v0 = hp[lane], v1 = hp[lane + 32];
    float as = v0 * a_src[head * 64 + lane] + v1 * a_src[head * 64 + lane + 32];
    float ad = v0 * a_dst[head * 64 + lane] + v1 * a_dst[head * 64 + lane + 32];
#pragma unroll
    for (int off = 16; off; off >>= 1) {
        as += __shfl_xor_sync(0xFFFFFFFFu, as, off);
        ad += __shfl_xor_sync(0xFFFFFFFFu, ad, off);
    }
    if (lane == 0) {
        s[w] = as;
        t[w] = ad;
    }
}

// ---------------- GAT aggregation: one block per dst node ----------------
template <int H, bool RELU>
__global__ void __launch_bounds__(H * 64) k_agg(const float* __restrict__ hin,
                                                const float* __restrict__ s,
                                                const float* __restrict__ t,
                                                const int* __restrict__ rowptr,
                                                const int* __restrict__ col,
                                                const float* __restrict__ bias,
                                                float* __restrict__ out) {
    constexpr int W = H * 64;
    constexpr int CH = 128;
    __shared__ float sh_m[H];
    __shared__ float sh_inv[H];
    __shared__ float red[W / 32];
    __shared__ int sh_src[CH];
    __shared__ float sh_al[CH * H];

    int node = blockIdx.x;
    int tid = threadIdx.x;
    int lane = tid & 31, warp = tid >> 5;
    int start = rowptr[node];
    int deg = rowptr[node + 1] - start;

    float tn[H];
#pragma unroll
    for (int h = 0; h < H; h++) tn[h] = t[node * H + h];

    // ---- pass 1: segment max per head ----
    float mx[H];
#pragma unroll
    for (int h = 0; h < H; h++) mx[h] = -1e30f;
    for (int k = tid; k < deg; k += W) {
        int src = col[start + k];
#pragma unroll
        for (int h = 0; h < H; h++) {
            float e = s[src * H + h] + tn[h];
            e = e > 0.f ? e : NEG_SLOPE * e;
            mx[h] = fmaxf(mx[h], e);
        }
    }
#pragma unroll
    for (int h = 0; h < H; h++) {
        float v = mx[h];
#pragma unroll
        for (int off = 16; off; off >>= 1) v = fmaxf(v, __shfl_xor_sync(0xFFFFFFFFu, v, off));
        if (lane == 0) red[warp] = v;
        __syncthreads();
        if (tid == 0) {
            float r = red[0];
            for (int w = 1; w < W / 32; w++) r = fmaxf(r, red[w]);
            sh_m[h] = r;
        }
        __syncthreads();
    }

    // ---- pass 2: sum of exp ----
    float sum[H];
#pragma unroll
    for (int h = 0; h < H; h++) sum[h] = 0.f;
    for (int k = tid; k < deg; k += W) {
        int src = col[start + k];
#pragma unroll
        for (int h = 0; h < H; h++) {
            float e = s[src * H + h] + tn[h];
            e = e > 0.f ? e : NEG_SLOPE * e;
            sum[h] += __expf(e - sh_m[h]);
        }
    }
#pragma unroll
    for (int h = 0; h < H; h++) {
        float v = sum[h];
#pragma unroll
        for (int off = 16; off; off >>= 1) v += __shfl_xor_sync(0xFFFFFFFFu, v, off);
        if (lane == 0) red[warp] = v;
        __syncthreads();
        if (tid == 0) {
            float r = red[0];
            for (int w = 1; w < W / 32; w++) r += red[w];
            sh_inv[h] = 1.f / (r + 1e-16f);
        }
        __syncthreads();
    }

    // ---- pass 3: weighted gather-sum, chunked through shared ----
    float acc = 0.f;
    int myhead = (H == 2) ? (tid >> 6) : 0;
    for (int base = 0; base < deg; base += CH) {
        int nk = min(CH, deg - base);
        for (int k = tid; k < nk * H; k += W) {
            int e_idx = (H == 2) ? (k >> 1) : k;
            int hh = (H == 2) ? (k & 1) : 0;
            int src = col[start + base + e_idx];
            float e = s[src * H + hh] + tn[hh];
            e = e > 0.f ? e : NEG_SLOPE * e;
            sh_al[e_idx * H + hh] = __expf(e - sh_m[hh]) * sh_inv[hh];
            if (hh == 0) sh_src[e_idx] = src;
        }
        __syncthreads();
#pragma unroll 4
        for (int e2 = 0; e2 < nk; e2++) {
            acc += hin[(size_t)sh_src[e2] * W + tid] * sh_al[e2 * H + myhead];
        }
        __syncthreads();
    }

    float v = acc + bias[tid];
    if (RELU) v = fmaxf(v, 0.f);
    out[(size_t)node * W + tid] = v;
}

// ---------------- host launch ----------------
extern "C" void kernel_launch(void* const* d_in, const int* in_sizes, int n_in,
                              void* d_out, int out_size) {
    const float* x     = (const float*)d_in[0];
    const int*   ei    = (const int*)d_in[1];
    const float* W0    = (const float*)d_in[2];
    const float* as0   = (const float*)d_in[3];
    const float* ad0   = (const float*)d_in[4];
    const float* b0    = (const float*)d_in[5];
    const float* W1    = (const float*)d_in[6];
    const float* as1   = (const float*)d_in[7];
    const float* ad1   = (const float*)d_in[8];
    const float* b1    = (const float*)d_in[9];
    const float* W2    = (const float*)d_in[10];
    const float* as2   = (const float*)d_in[11];
    const float* ad2   = (const float*)d_in[12];
    const float* b2    = (const float*)d_in[13];
    const float* Wv    = (const float*)d_in[14];
    const float* bv    = (const float*)d_in[15];
    const float* Wt    = (const float*)d_in[16];
    const float* bt    = (const float*)d_in[17];

    int N = in_sizes[0] / 512;
    int E = in_sizes[1] / 2;

    float* out = (float*)d_out;
    float* h_out = out;
    float* vis = out + (size_t)N * 64;
    float* txt = out + (size_t)N * 64 * 2;

    float *h0, *h1, *sA, *tA;
    int *deg, *rowptr, *cursor, *colA;
    cudaGetSymbolAddress((void**)&h0, g_h0);
    cudaGetSymbolAddress((void**)&h1, g_h1);
    cudaGetSymbolAddress((void**)&sA, g_s);
    cudaGetSymbolAddress((void**)&tA, g_t);
    cudaGetSymbolAddress((void**)&deg, g_deg);
    cudaGetSymbolAddress((void**)&rowptr, g_rowptr);
    cudaGetSymbolAddress((void**)&cursor, g_cursor);
    cudaGetSymbolAddress((void**)&colA, g_col);

    // ---- CSR build (dst-major, self loop first in each row) ----
    k_init_deg<<<(N + 255) / 256, 256>>>(deg, N);
    k_hist<<<(E + 255) / 256, 256>>>(ei, E, deg);
    k_scan<<<1, 1024>>>(deg, rowptr, N);
    k_init_cursor<<<(N + 255) / 256, 256>>>(rowptr, cursor, colA, N);
    k_scatter<<<(E + 255) / 256, 256>>>(ei, E, cursor, colA);

    int gblk = (N + 127) / 128;

    // ---- layer 0: 512 -> 2x64 ----
    k_sgemm<128><<<gblk, 256>>>(x, W0, h0, N, 512, nullptr, 0);
    k_st<2><<<(N * 2 * 32 + 255) / 256, 256>>>(h0, as0, ad0, sA, tA, N);
    k_agg<2, true><<<N, 128>>>(h0, sA, tA, rowptr, colA, b0, h1);

    // ---- layer 1: 128 -> 2x64 ----
    k_sgemm<128><<<gblk, 256>>>(h1, W1, h0, N, 128, nullptr, 0);
    k_st<2><<<(N * 2 * 32 + 255) / 256, 256>>>(h0, as1, ad1, sA, tA, N);
    k_agg<2, true><<<N, 128>>>(h0, sA, tA, rowptr, colA, b1, h1);

    // ---- layer 2: 128 -> 64 (heads=1, no relu) ----
    k_sgemm<64><<<gblk, 256>>>(h1, W2, h0, N, 128, nullptr, 0);
    k_st<1><<<(N * 32 + 255) / 256, 256>>>(h0, as2, ad2, sA, tA, N);
    k_agg<1, false><<<N, 64>>>(h0, sA, tA, rowptr, colA, b2, h_out);

    // ---- MLP heads ----
    k_sgemm<64><<<gblk, 256>>>(h_out, Wv, vis, N, 64, bv, 1);
    k_sgemm<64><<<gblk, 256>>>(h_out, Wt, txt, N, 64, bt, 1);
}